// round 1
// baseline (speedup 1.0000x reference)
#include <cuda_runtime.h>
#include <math.h>

#define Nb 2
#define T  2048
#define H  256
#define NH 8
#define D  32
#define SCALE 17.677669529663689f   /* (1/sqrt(32)) / 0.01 */
#define NEGBIG (-1e30f)

/* Scratch: __device__ globals (no allocations allowed). */
__device__ __align__(16) float g_Qh[Nb*NH*T*D];   /* [n][h][t][d] */
__device__ __align__(16) float g_Kh[Nb*NH*T*D];
__device__ __align__(16) float g_Vh[Nb*NH*T*D];
__device__ __align__(16) float g_ctx[Nb*T*H];     /* [n][t][h*D+d] */
__device__ float g_kmask[Nb*T];
__device__ float g_qmask[Nb*T];

/* ------------------------------------------------------------------ */
/* Masks: sign(sum |x|) per (n,t) row of original Q (y=0) / K (y=1).  */
__global__ void mask_kernel(const float* __restrict__ Q,
                            const float* __restrict__ K) {
    int row = blockIdx.x;                    /* 0..Nb*T-1 */
    const float* src = blockIdx.y ? K : Q;
    float* dst       = blockIdx.y ? g_kmask : g_qmask;
    int t = threadIdx.x;                     /* 128 threads */
    float s = fabsf(src[row*H + t]) + fabsf(src[row*H + t + 128]);
    __shared__ float red[4];
    #pragma unroll
    for (int o = 16; o; o >>= 1) s += __shfl_xor_sync(0xffffffffu, s, o);
    if ((t & 31) == 0) red[t >> 5] = s;
    __syncthreads();
    if (t == 0) {
        float tot = red[0] + red[1] + red[2] + red[3];
        dst[row] = (tot != 0.0f) ? 1.0f : 0.0f;
    }
}

/* ------------------------------------------------------------------ */
/* Fused projection: dst[n][h][t][d] = relu(X @ W + b), head-major.   */
/* Grid: (H/64, M/64, 3), 256 threads, 64x64 tile, 4x4 per thread.    */
__global__ void __launch_bounds__(256) proj_kernel(
        const float* __restrict__ Q, const float* __restrict__ K,
        const float* __restrict__ V,
        const float* __restrict__ Wq, const float* __restrict__ Wk,
        const float* __restrict__ Wv,
        const float* __restrict__ bq, const float* __restrict__ bk,
        const float* __restrict__ bv) {
    int sel = blockIdx.z;
    const float* X = (sel == 0) ? Q  : (sel == 1) ? K  : V;
    const float* W = (sel == 0) ? Wq : (sel == 1) ? Wk : Wv;
    const float* b = (sel == 0) ? bq : (sel == 1) ? bk : bv;
    float* dst     = (sel == 0) ? g_Qh : (sel == 1) ? g_Kh : g_Vh;

    int m0 = blockIdx.y * 64;
    int n0 = blockIdx.x * 64;

    __shared__ __align__(16) float Xst[32][68];  /* [k][m] transposed */
    __shared__ __align__(16) float Wsh[32][68];  /* [k][n]            */

    int tid = threadIdx.x;
    int ty = tid >> 4, tx = tid & 15;
    float acc[4][4] = {};

    for (int k0 = 0; k0 < H; k0 += 32) {
        __syncthreads();
        #pragma unroll
        for (int it = 0; it < 8; ++it) {
            int e = tid + it * 256;
            int r = e >> 5, c = e & 31;
            Xst[c][r] = X[(m0 + r) * H + k0 + c];
            int r2 = e >> 6, c2 = e & 63;
            Wsh[r2][c2] = W[(k0 + r2) * H + n0 + c2];
        }
        __syncthreads();
        #pragma unroll
        for (int kk = 0; kk < 32; ++kk) {
            float4 a  = *(const float4*)&Xst[kk][4 * ty];
            float4 bb = *(const float4*)&Wsh[kk][4 * tx];
            acc[0][0] += a.x*bb.x; acc[0][1] += a.x*bb.y; acc[0][2] += a.x*bb.z; acc[0][3] += a.x*bb.w;
            acc[1][0] += a.y*bb.x; acc[1][1] += a.y*bb.y; acc[1][2] += a.y*bb.z; acc[1][3] += a.y*bb.w;
            acc[2][0] += a.z*bb.x; acc[2][1] += a.z*bb.y; acc[2][2] += a.z*bb.z; acc[2][3] += a.z*bb.w;
            acc[3][0] += a.w*bb.x; acc[3][1] += a.w*bb.y; acc[3][2] += a.w*bb.z; acc[3][3] += a.w*bb.w;
        }
    }

    int c0 = n0 + 4 * tx;           /* output column, 4-aligned, same head */
    int hh = c0 >> 5, d0 = c0 & 31;
    float b0 = b[c0+0], b1 = b[c0+1], b2 = b[c0+2], b3 = b[c0+3];
    #pragma unroll
    for (int i = 0; i < 4; ++i) {
        int m  = m0 + 4 * ty + i;
        int nn = m >> 11, tt = m & 2047;
        float4 o;
        o.x = fmaxf(acc[i][0] + b0, 0.0f);
        o.y = fmaxf(acc[i][1] + b1, 0.0f);
        o.z = fmaxf(acc[i][2] + b2, 0.0f);
        o.w = fmaxf(acc[i][3] + b3, 0.0f);
        *(float4*)&dst[(((nn * NH) + hh) * T + tt) * D + d0] = o;
    }
}

/* ------------------------------------------------------------------ */
/* Flash attention. Grid (T/64, NH, Nb), 256 threads.                 */
/* Phase1: S = Q K^T (4x4/thread), online softmax, P -> smem.         */
/* Phase2: O[q][d] += P[q][k] V[k][d] (warp=8 q-rows, lane=d).        */
__global__ void __launch_bounds__(256) attn_kernel() {
    int q0 = blockIdx.x * 64;
    int hh = blockIdx.y, nn = blockIdx.z;
    const float* Qh = g_Qh + (size_t)(nn * NH + hh) * T * D;
    const float* Kh = g_Kh + (size_t)(nn * NH + hh) * T * D;
    const float* Vh = g_Vh + (size_t)(nn * NH + hh) * T * D;

    __shared__ __align__(16) float Qt[32][68];   /* [d][q] */
    __shared__ __align__(16) float Kt[32][68];   /* [d][k] */
    __shared__ __align__(16) float Vt[32][68];   /* [d][k] */
    __shared__ __align__(16) float Ps[64][68];   /* [q][k] */
    __shared__ float m_s[64], l_s[64], fs_s[64];

    int tid = threadIdx.x;
    int qg = tid >> 4, kg = tid & 15;
    int w  = tid >> 5, d  = tid & 31;

    #pragma unroll
    for (int it = 0; it < 8; ++it) {
        int e = tid + it * 256;
        int r = e >> 5, c = e & 31;
        Qt[c][r] = Qh[(q0 + r) * D + c];
    }
    if (tid < 64) { m_s[tid] = -1e30f; l_s[tid] = 0.0f; fs_s[tid] = 0.0f; }
    float O[8] = {0,0,0,0,0,0,0,0};

    for (int kt = 0; kt < T / 64; ++kt) {
        int k0 = kt * 64;
        __syncthreads();
        #pragma unroll
        for (int it = 0; it < 8; ++it) {
            int e = tid + it * 256;
            int r = e >> 5, c = e & 31;
            Kt[c][r] = Kh[(k0 + r) * D + c];
            Vt[c][r] = Vh[(k0 + r) * D + c];
        }
        __syncthreads();

        /* ---- Phase 1: S = Q K^T, online softmax ---- */
        float acc[4][4] = {};
        #pragma unroll
        for (int dd = 0; dd < 32; ++dd) {
            float4 a  = *(const float4*)&Qt[dd][4 * qg];
            float4 bb = *(const float4*)&Kt[dd][4 * kg];
            acc[0][0] += a.x*bb.x; acc[0][1] += a.x*bb.y; acc[0][2] += a.x*bb.z; acc[0][3] += a.x*bb.w;
            acc[1][0] += a.y*bb.x; acc[1][1] += a.y*bb.y; acc[1][2] += a.y*bb.z; acc[1][3] += a.y*bb.w;
            acc[2][0] += a.z*bb.x; acc[2][1] += a.z*bb.y; acc[2][2] += a.z*bb.z; acc[2][3] += a.z*bb.w;
            acc[3][0] += a.w*bb.x; acc[3][1] += a.w*bb.y; acc[3][2] += a.w*bb.z; acc[3][3] += a.w*bb.w;
        }
        float msk[4];
        #pragma unroll
        for (int j = 0; j < 4; ++j)
            msk[j] = g_kmask[nn * T + k0 + 4 * kg + j];

        #pragma unroll
        for (int i = 0; i < 4; ++i) {
            int q = 4 * qg + i;
            float s0 = (msk[0] != 0.0f) ? acc[i][0] * SCALE : NEGBIG;
            float s1 = (msk[1] != 0.0f) ? acc[i][1] * SCALE : NEGBIG;
            float s2 = (msk[2] != 0.0f) ? acc[i][2] * SCALE : NEGBIG;
            float s3 = (msk[3] != 0.0f) ? acc[i][3] * SCALE : NEGBIG;
            float mx = fmaxf(fmaxf(s0, s1), fmaxf(s2, s3));
            #pragma unroll
            for (int o = 8; o; o >>= 1)
                mx = fmaxf(mx, __shfl_xor_sync(0xffffffffu, mx, o));
            float mo = m_s[q];
            float nm = fmaxf(mo, mx);
            float p0 = __expf(s0 - nm), p1 = __expf(s1 - nm);
            float p2 = __expf(s2 - nm), p3 = __expf(s3 - nm);
            float sum = (p0 + p1) + (p2 + p3);
            #pragma unroll
            for (int o = 8; o; o >>= 1)
                sum += __shfl_xor_sync(0xffffffffu, sum, o);
            /* key Tk-1 participates in softmax denom but not in ctx */
            float4 pw;
            pw.x = (k0 + 4*kg + 0 == T - 1) ? 0.0f : p0;
            pw.y = (k0 + 4*kg + 1 == T - 1) ? 0.0f : p1;
            pw.z = (k0 + 4*kg + 2 == T - 1) ? 0.0f : p2;
            pw.w = (k0 + 4*kg + 3 == T - 1) ? 0.0f : p3;
            *(float4*)&Ps[q][4 * kg] = pw;
            if (kg == 0) {
                float f = __expf(mo - nm);
                l_s[q]  = l_s[q] * f + sum;
                m_s[q]  = nm;
                fs_s[q] = f;
            }
        }
        __syncthreads();

        /* ---- Phase 2: O += P V ---- */
        #pragma unroll
        for (int i = 0; i < 8; ++i) O[i] *= fs_s[8 * w + i];
        #pragma unroll
        for (int k = 0; k < 64; k += 4) {
            float4 v = *(const float4*)&Vt[d][k];
            #pragma unroll
            for (int i = 0; i < 8; ++i) {
                float4 p = *(const float4*)&Ps[8 * w + i][k];
                O[i] += p.x * v.x;
                O[i] += p.y * v.y;
                O[i] += p.z * v.z;
                O[i] += p.w * v.w;
            }
        }
    }

    #pragma unroll
    for (int i = 0; i < 8; ++i) {
        int q = 8 * w + i;
        float qm  = g_qmask[nn * T + q0 + q];
        float val = O[i] / l_s[q] * qm;
        g_ctx[(size_t)(nn * T + q0 + q) * H + hh * D + d] = val;
    }
}

/* ------------------------------------------------------------------ */
/* LayerNorm over H=256 per row + weight output.                      */
__global__ void __launch_bounds__(256) ln_kernel(
        const float* __restrict__ gamma, const float* __restrict__ beta,
        float* __restrict__ out, float* __restrict__ wout) {
    int row = blockIdx.x;            /* 0..Nb*T-1 */
    int t = threadIdx.x;             /* 256 */
    float x = g_ctx[(size_t)row * H + t];
    __shared__ float rs[8], rq[8];
    float s = x, q = x * x;
    #pragma unroll
    for (int o = 16; o; o >>= 1) {
        s += __shfl_xor_sync(0xffffffffu, s, o);
        q += __shfl_xor_sync(0xffffffffu, q, o);
    }
    if ((t & 31) == 0) { rs[t >> 5] = s; rq[t >> 5] = q; }
    __syncthreads();
    float ts = 0.0f, tq = 0.0f;
    #pragma unroll
    for (int i = 0; i < 8; ++i) { ts += rs[i]; tq += rq[i]; }
    float mu  = ts * (1.0f / H);
    float var = tq * (1.0f / H) - mu * mu;
    float inv = rsqrtf(var + 1e-5f);
    out[(size_t)row * H + t] = (x - mu) * inv * gamma[t] + beta[t];
    if (t == 0)
        wout[row] = g_qmask[row] * (1.0f / (float)T);  /* softmax rows sum to 1 */
}

/* ------------------------------------------------------------------ */
extern "C" void kernel_launch(void* const* d_in, const int* in_sizes, int n_in,
                              void* d_out, int out_size) {
    const float* Q  = (const float*)d_in[0];
    const float* K  = (const float*)d_in[1];
    const float* V  = (const float*)d_in[2];
    const float* Wq = (const float*)d_in[3];
    const float* bq = (const float*)d_in[4];
    const float* Wk = (const float*)d_in[5];
    const float* bk = (const float*)d_in[6];
    const float* Wv = (const float*)d_in[7];
    const float* bv = (const float*)d_in[8];
    const float* gamma = (const float*)d_in[9];
    const float* beta  = (const float*)d_in[10];

    float* out  = (float*)d_out;
    float* wout = out + (out_size - Nb * T);   /* weight tail: [Nb*T] */

    mask_kernel<<<dim3(Nb * T, 2), 128>>>(Q, K);
    proj_kernel<<<dim3(H / 64, (Nb * T) / 64, 3), 256>>>(Q, K, V,
                                                         Wq, Wk, Wv,
                                                         bq, bk, bv);
    attn_kernel<<<dim3(T / 64, NH, Nb), 256>>>();
    ln_kernel<<<Nb * T, 256>>>(gamma, beta, out, wout);
}

// round 2
// speedup vs baseline: 1.0318x; 1.0318x over previous
#include <cuda_runtime.h>
#include <math.h>

#define Nb 2
#define T  2048
#define H  256
#define NH 8
#define D  32
#define SCALE 17.677669529663689f   /* (1/sqrt(32)) / 0.01 */
#define NEGBIG (-1e30f)

typedef unsigned long long u64;

/* ---- packed f32x2 helpers (ptxas never emits FFMA2 from C++) ---- */
__device__ __forceinline__ void fma2(u64& d, u64 a, u64 b) {
    asm("fma.rn.f32x2 %0, %1, %2, %0;" : "+l"(d) : "l"(a), "l"(b));
}
__device__ __forceinline__ u64 pack2(float x, float y) {
    u64 r; asm("mov.b64 %0, {%1, %2};" : "=l"(r) : "f"(x), "f"(y)); return r;
}
__device__ __forceinline__ float2 unpack2(u64 v) {
    float2 f; asm("mov.b64 {%0, %1}, %2;" : "=f"(f.x), "=f"(f.y) : "l"(v)); return f;
}
__device__ __forceinline__ u64 mul2(u64 a, u64 b) {
    u64 r; asm("mul.rn.f32x2 %0, %1, %2;" : "=l"(r) : "l"(a), "l"(b)); return r;
}

/* Scratch: __device__ globals (no allocations allowed). */
__device__ __align__(16) float g_Qh[Nb*NH*T*D];   /* [n][h][t][d] */
__device__ __align__(16) float g_Kh[Nb*NH*T*D];
__device__ __align__(16) float g_Vh[Nb*NH*T*D];
__device__ __align__(16) float g_ctx[Nb*T*H];     /* [n][t][h*D+d] */
__device__ float g_kmask[Nb*T];
__device__ float g_qmask[Nb*T];

/* ------------------------------------------------------------------ */
__global__ void mask_kernel(const float* __restrict__ Q,
                            const float* __restrict__ K) {
    int row = blockIdx.x;
    const float* src = blockIdx.y ? K : Q;
    float* dst       = blockIdx.y ? g_kmask : g_qmask;
    int t = threadIdx.x;                     /* 128 threads */
    float s = fabsf(src[row*H + t]) + fabsf(src[row*H + t + 128]);
    __shared__ float red[4];
    #pragma unroll
    for (int o = 16; o; o >>= 1) s += __shfl_xor_sync(0xffffffffu, s, o);
    if ((t & 31) == 0) red[t >> 5] = s;
    __syncthreads();
    if (t == 0) {
        float tot = red[0] + red[1] + red[2] + red[3];
        dst[row] = (tot != 0.0f) ? 1.0f : 0.0f;
    }
}

/* ------------------------------------------------------------------ */
/* Fused projection: dst[n][h][t][d] = relu(X @ W + b), head-major.   */
__global__ void __launch_bounds__(256) proj_kernel(
        const float* __restrict__ Q, const float* __restrict__ K,
        const float* __restrict__ V,
        const float* __restrict__ Wq, const float* __restrict__ Wk,
        const float* __restrict__ Wv,
        const float* __restrict__ bq, const float* __restrict__ bk,
        const float* __restrict__ bv) {
    int sel = blockIdx.z;
    const float* X = (sel == 0) ? Q  : (sel == 1) ? K  : V;
    const float* W = (sel == 0) ? Wq : (sel == 1) ? Wk : Wv;
    const float* b = (sel == 0) ? bq : (sel == 1) ? bk : bv;
    float* dst     = (sel == 0) ? g_Qh : (sel == 1) ? g_Kh : g_Vh;

    int m0 = blockIdx.y * 64;
    int n0 = blockIdx.x * 64;

    __shared__ __align__(16) float Xst[32][68];  /* [k][m] transposed */
    __shared__ __align__(16) float Wsh[32][68];  /* [k][n]            */

    int tid = threadIdx.x;
    int ty = tid >> 4, tx = tid & 15;
    u64 acc2[4][2] = {};

    for (int k0 = 0; k0 < H; k0 += 32) {
        __syncthreads();
        #pragma unroll
        for (int it = 0; it < 8; ++it) {
            int e = tid + it * 256;
            int r = e >> 5, c = e & 31;
            Xst[c][r] = X[(m0 + r) * H + k0 + c];
            int r2 = e >> 6, c2 = e & 63;
            Wsh[r2][c2] = W[(k0 + r2) * H + n0 + c2];
        }
        __syncthreads();
        #pragma unroll
        for (int kk = 0; kk < 32; ++kk) {
            float4 a = *(const float4*)&Xst[kk][4 * ty];
            ulonglong2 bb = *(const ulonglong2*)&Wsh[kk][4 * tx];
            u64 a0 = pack2(a.x, a.x), a1 = pack2(a.y, a.y);
            u64 a2 = pack2(a.z, a.z), a3 = pack2(a.w, a.w);
            fma2(acc2[0][0], a0, bb.x); fma2(acc2[0][1], a0, bb.y);
            fma2(acc2[1][0], a1, bb.x); fma2(acc2[1][1], a1, bb.y);
            fma2(acc2[2][0], a2, bb.x); fma2(acc2[2][1], a2, bb.y);
            fma2(acc2[3][0], a3, bb.x); fma2(acc2[3][1], a3, bb.y);
        }
    }

    int c0 = n0 + 4 * tx;
    int hh = c0 >> 5, d0 = c0 & 31;
    float b0 = b[c0+0], b1 = b[c0+1], b2 = b[c0+2], b3 = b[c0+3];
    #pragma unroll
    for (int i = 0; i < 4; ++i) {
        int m  = m0 + 4 * ty + i;
        int nn = m >> 11, tt = m & 2047;
        float2 lo = unpack2(acc2[i][0]), hi = unpack2(acc2[i][1]);
        float4 o;
        o.x = fmaxf(lo.x + b0, 0.0f);
        o.y = fmaxf(lo.y + b1, 0.0f);
        o.z = fmaxf(hi.x + b2, 0.0f);
        o.w = fmaxf(hi.y + b3, 0.0f);
        *(float4*)&dst[(((nn * NH) + hh) * T + tt) * D + d0] = o;
    }
}

/* ------------------------------------------------------------------ */
/* Flash attention. Grid (T/64, NH, Nb), 256 threads.                 */
__global__ void __launch_bounds__(256) attn_kernel() {
    int q0 = blockIdx.x * 64;
    int hh = blockIdx.y, nn = blockIdx.z;
    const float* Qh = g_Qh + (size_t)(nn * NH + hh) * T * D;
    const float* Kh = g_Kh + (size_t)(nn * NH + hh) * T * D;
    const float* Vh = g_Vh + (size_t)(nn * NH + hh) * T * D;

    __shared__ __align__(16) float Qt[32][68];   /* [d][q] */
    __shared__ __align__(16) float Kt[32][68];   /* [d][k] */
    __shared__ __align__(16) float Vt[32][68];   /* [d][k] */
    __shared__ __align__(16) float Ps[64][68];   /* [q][k] */
    __shared__ float m_s[64], l_s[64], fs_s[64];

    int tid = threadIdx.x;
    int qg = tid >> 4, kg = tid & 15;
    int w  = tid >> 5, d  = tid & 31;

    #pragma unroll
    for (int it = 0; it < 8; ++it) {
        int e = tid + it * 256;
        int r = e >> 5, c = e & 31;
        Qt[c][r] = Qh[(q0 + r) * D + c];
    }
    if (tid < 64) { m_s[tid] = -1e30f; l_s[tid] = 0.0f; fs_s[tid] = 0.0f; }
    u64 O2[8] = {};

    for (int kt = 0; kt < T / 64; ++kt) {
        int k0 = kt * 64;
        __syncthreads();
        #pragma unroll
        for (int it = 0; it < 8; ++it) {
            int e = tid + it * 256;
            int r = e >> 5, c = e & 31;
            Kt[c][r] = Kh[(k0 + r) * D + c];
            Vt[c][r] = Vh[(k0 + r) * D + c];
        }
        __syncthreads();

        /* ---- Phase 1: S = Q K^T via packed FFMA2, online softmax ---- */
        u64 acc2[4][2] = {};
        #pragma unroll
        for (int dd = 0; dd < 32; ++dd) {
            float4 a = *(const float4*)&Qt[dd][4 * qg];
            ulonglong2 bb = *(const ulonglong2*)&Kt[dd][4 * kg];
            u64 a0 = pack2(a.x, a.x), a1 = pack2(a.y, a.y);
            u64 a2 = pack2(a.z, a.z), a3 = pack2(a.w, a.w);
            fma2(acc2[0][0], a0, bb.x); fma2(acc2[0][1], a0, bb.y);
            fma2(acc2[1][0], a1, bb.x); fma2(acc2[1][1], a1, bb.y);
            fma2(acc2[2][0], a2, bb.x); fma2(acc2[2][1], a2, bb.y);
            fma2(acc2[3][0], a3, bb.x); fma2(acc2[3][1], a3, bb.y);
        }
        float msk[4];
        #pragma unroll
        for (int j = 0; j < 4; ++j)
            msk[j] = g_kmask[nn * T + k0 + 4 * kg + j];

        #pragma unroll
        for (int i = 0; i < 4; ++i) {
            int q = 4 * qg + i;
            float2 lo = unpack2(acc2[i][0]), hi = unpack2(acc2[i][1]);
            float s0 = (msk[0] != 0.0f) ? lo.x * SCALE : NEGBIG;
            float s1 = (msk[1] != 0.0f) ? lo.y * SCALE : NEGBIG;
            float s2 = (msk[2] != 0.0f) ? hi.x * SCALE : NEGBIG;
            float s3 = (msk[3] != 0.0f) ? hi.y * SCALE : NEGBIG;
            float mx = fmaxf(fmaxf(s0, s1), fmaxf(s2, s3));
            #pragma unroll
            for (int o = 8; o; o >>= 1)
                mx = fmaxf(mx, __shfl_xor_sync(0xffffffffu, mx, o));
            float mo = m_s[q];
            float nm = fmaxf(mo, mx);
            float p0 = __expf(s0 - nm), p1 = __expf(s1 - nm);
            float p2 = __expf(s2 - nm), p3 = __expf(s3 - nm);
            float sum = (p0 + p1) + (p2 + p3);
            #pragma unroll
            for (int o = 8; o; o >>= 1)
                sum += __shfl_xor_sync(0xffffffffu, sum, o);
            /* key Tk-1 participates in softmax denom but not in ctx */
            float4 pw;
            pw.x = (k0 + 4*kg + 0 == T - 1) ? 0.0f : p0;
            pw.y = (k0 + 4*kg + 1 == T - 1) ? 0.0f : p1;
            pw.z = (k0 + 4*kg + 2 == T - 1) ? 0.0f : p2;
            pw.w = (k0 + 4*kg + 3 == T - 1) ? 0.0f : p3;
            *(float4*)&Ps[q][4 * kg] = pw;
            if (kg == 0) {
                float f = __expf(mo - nm);
                l_s[q]  = l_s[q] * f + sum;
                m_s[q]  = nm;
                fs_s[q] = f;
            }
        }
        __syncthreads();

        /* ---- Phase 2: O += P V via packed FFMA2 (lo/hi partial sums) ---- */
        #pragma unroll
        for (int i = 0; i < 8; ++i) {
            float f = fs_s[8 * w + i];
            O2[i] = mul2(O2[i], pack2(f, f));
        }
        #pragma unroll
        for (int k = 0; k < 64; k += 4) {
            ulonglong2 v2 = *(const ulonglong2*)&Vt[d][k];
            #pragma unroll
            for (int i = 0; i < 8; ++i) {
                ulonglong2 p2 = *(const ulonglong2*)&Ps[8 * w + i][k];
                fma2(O2[i], p2.x, v2.x);
                fma2(O2[i], p2.y, v2.y);
            }
        }
    }

    #pragma unroll
    for (int i = 0; i < 8; ++i) {
        int q = 8 * w + i;
        float qm  = g_qmask[nn * T + q0 + q];
        float2 oo = unpack2(O2[i]);
        float val = (oo.x + oo.y) / l_s[q] * qm;
        g_ctx[(size_t)(nn * T + q0 + q) * H + hh * D + d] = val;
    }
}

/* ------------------------------------------------------------------ */
__global__ void __launch_bounds__(256) ln_kernel(
        const float* __restrict__ gamma, const float* __restrict__ beta,
        float* __restrict__ out, float* __restrict__ wout) {
    int row = blockIdx.x;
    int t = threadIdx.x;
    float x = g_ctx[(size_t)row * H + t];
    __shared__ float rs[8], rq[8];
    float s = x, q = x * x;
    #pragma unroll
    for (int o = 16; o; o >>= 1) {
        s += __shfl_xor_sync(0xffffffffu, s, o);
        q += __shfl_xor_sync(0xffffffffu, q, o);
    }
    if ((t & 31) == 0) { rs[t >> 5] = s; rq[t >> 5] = q; }
    __syncthreads();
    float ts = 0.0f, tq = 0.0f;
    #pragma unroll
    for (int i = 0; i < 8; ++i) { ts += rs[i]; tq += rq[i]; }
    float mu  = ts * (1.0f / H);
    float var = tq * (1.0f / H) - mu * mu;
    float inv = rsqrtf(var + 1e-5f);
    out[(size_t)row * H + t] = (x - mu) * inv * gamma[t] + beta[t];
    if (t == 0)
        wout[row] = g_qmask[row] * (1.0f / (float)T);
}

/* ------------------------------------------------------------------ */
extern "C" void kernel_launch(void* const* d_in, const int* in_sizes, int n_in,
                              void* d_out, int out_size) {
    const float* Q  = (const float*)d_in[0];
    const float* K  = (const float*)d_in[1];
    const float* V  = (const float*)d_in[2];
    const float* Wq = (const float*)d_in[3];
    const float* bq = (const float*)d_in[4];
    const float* Wk = (const float*)d_in[5];
    const float* bk = (const float*)d_in[6];
    const float* Wv = (const float*)d_in[7];
    const float* bv = (const float*)d_in[8];
    const float* gamma = (const float*)d_in[9];
    const float* beta  = (const float*)d_in[10];

    float* out  = (float*)d_out;
    float* wout = out + (out_size - Nb * T);

    mask_kernel<<<dim3(Nb * T, 2), 128>>>(Q, K);
    proj_kernel<<<dim3(H / 64, (Nb * T) / 64, 3), 256>>>(Q, K, V,
                                                         Wq, Wk, Wv,
                                                         bq, bk, bv);
    attn_kernel<<<dim3(T / 64, NH, Nb), 256>>>();
    ln_kernel<<<Nb * T, 256>>>(gamma, beta, out, wout);
}

// round 3
// speedup vs baseline: 1.0330x; 1.0012x over previous
#include <cuda_runtime.h>
#include <math.h>

#define Nb 2
#define T  2048
#define H  256
#define NH 8
#define D  32
#define SCALE 17.677669529663689f   /* (1/sqrt(32)) / 0.01 */
#define NEGBIG (-1e30f)

typedef unsigned long long u64;

/* ---- packed f32x2 helpers (ptxas never emits FFMA2 from C++) ---- */
__device__ __forceinline__ void fma2(u64& d, u64 a, u64 b) {
    asm("fma.rn.f32x2 %0, %1, %2, %0;" : "+l"(d) : "l"(a), "l"(b));
}
__device__ __forceinline__ u64 pack2(float x, float y) {
    u64 r; asm("mov.b64 %0, {%1, %2};" : "=l"(r) : "f"(x), "f"(y)); return r;
}
__device__ __forceinline__ float2 unpack2(u64 v) {
    float2 f; asm("mov.b64 {%0, %1}, %2;" : "=f"(f.x), "=f"(f.y) : "l"(v)); return f;
}
__device__ __forceinline__ u64 mul2(u64 a, u64 b) {
    u64 r; asm("mul.rn.f32x2 %0, %1, %2;" : "=l"(r) : "l"(a), "l"(b)); return r;
}

/* Scratch: __device__ globals (no allocations allowed). */
__device__ __align__(16) float g_Qh[Nb*NH*T*D];   /* [n][h][t][d] */
__device__ __align__(16) float g_Kh[Nb*NH*T*D];
__device__ __align__(16) float g_Vh[Nb*NH*T*D];
__device__ __align__(16) float g_ctx[Nb*T*H];     /* [n][t][h*D+d] */
__device__ float g_kmask[Nb*T];
__device__ float g_qmask[Nb*T];

/* ------------------------------------------------------------------ */
__global__ void mask_kernel(const float* __restrict__ Q,
                            const float* __restrict__ K) {
    int row = blockIdx.x;
    const float* src = blockIdx.y ? K : Q;
    float* dst       = blockIdx.y ? g_kmask : g_qmask;
    int t = threadIdx.x;                     /* 128 threads */
    float s = fabsf(src[row*H + t]) + fabsf(src[row*H + t + 128]);
    __shared__ float red[4];
    #pragma unroll
    for (int o = 16; o; o >>= 1) s += __shfl_xor_sync(0xffffffffu, s, o);
    if ((t & 31) == 0) red[t >> 5] = s;
    __syncthreads();
    if (t == 0) {
        float tot = red[0] + red[1] + red[2] + red[3];
        dst[row] = (tot != 0.0f) ? 1.0f : 0.0f;
    }
}

/* ------------------------------------------------------------------ */
/* Fused projection: dst[n][h][t][d] = relu(X @ W + b), head-major.   */
__global__ void __launch_bounds__(256) proj_kernel(
        const float* __restrict__ Q, const float* __restrict__ K,
        const float* __restrict__ V,
        const float* __restrict__ Wq, const float* __restrict__ Wk,
        const float* __restrict__ Wv,
        const float* __restrict__ bq, const float* __restrict__ bk,
        const float* __restrict__ bv) {
    int sel = blockIdx.z;
    const float* X = (sel == 0) ? Q  : (sel == 1) ? K  : V;
    const float* W = (sel == 0) ? Wq : (sel == 1) ? Wk : Wv;
    const float* b = (sel == 0) ? bq : (sel == 1) ? bk : bv;
    float* dst     = (sel == 0) ? g_Qh : (sel == 1) ? g_Kh : g_Vh;

    int m0 = blockIdx.y * 64;
    int n0 = blockIdx.x * 64;

    __shared__ __align__(16) float Xst[32][68];  /* [k][m] transposed */
    __shared__ __align__(16) float Wsh[32][68];  /* [k][n]            */

    int tid = threadIdx.x;
    int ty = tid >> 4, tx = tid & 15;
    u64 acc2[4][2] = {};

    for (int k0 = 0; k0 < H; k0 += 32) {
        __syncthreads();
        #pragma unroll
        for (int it = 0; it < 8; ++it) {
            int e = tid + it * 256;
            int r = e >> 5, c = e & 31;
            Xst[c][r] = X[(m0 + r) * H + k0 + c];
            int r2 = e >> 6, c2 = e & 63;
            Wsh[r2][c2] = W[(k0 + r2) * H + n0 + c2];
        }
        __syncthreads();
        #pragma unroll
        for (int kk = 0; kk < 32; ++kk) {
            float4 a = *(const float4*)&Xst[kk][4 * ty];
            ulonglong2 bb = *(const ulonglong2*)&Wsh[kk][4 * tx];
            u64 a0 = pack2(a.x, a.x), a1 = pack2(a.y, a.y);
            u64 a2 = pack2(a.z, a.z), a3 = pack2(a.w, a.w);
            fma2(acc2[0][0], a0, bb.x); fma2(acc2[0][1], a0, bb.y);
            fma2(acc2[1][0], a1, bb.x); fma2(acc2[1][1], a1, bb.y);
            fma2(acc2[2][0], a2, bb.x); fma2(acc2[2][1], a2, bb.y);
            fma2(acc2[3][0], a3, bb.x); fma2(acc2[3][1], a3, bb.y);
        }
    }

    int c0 = n0 + 4 * tx;
    int hh = c0 >> 5, d0 = c0 & 31;
    float b0 = b[c0+0], b1 = b[c0+1], b2 = b[c0+2], b3 = b[c0+3];
    #pragma unroll
    for (int i = 0; i < 4; ++i) {
        int m  = m0 + 4 * ty + i;
        int nn = m >> 11, tt = m & 2047;
        float2 lo = unpack2(acc2[i][0]), hi = unpack2(acc2[i][1]);
        float4 o;
        o.x = fmaxf(lo.x + b0, 0.0f);
        o.y = fmaxf(lo.y + b1, 0.0f);
        o.z = fmaxf(hi.x + b2, 0.0f);
        o.w = fmaxf(hi.y + b3, 0.0f);
        *(float4*)&dst[(((nn * NH) + hh) * T + tt) * D + d0] = o;
    }
}

/* ------------------------------------------------------------------ */
/* Flash attention. Grid (T/64, NH, Nb), 256 threads, 4 blocks/SM.    */
/* Smem 53.5KB: Qtd(dup pairs) + Kt[d][k] + Vs[k][d] + Ps[q][k].      */
__global__ void __launch_bounds__(256, 4) attn_kernel() {
    int q0 = blockIdx.x * 64;
    int hh = blockIdx.y, nn = blockIdx.z;
    const float* Qh = g_Qh + (size_t)(nn * NH + hh) * T * D;
    const float* Kh = g_Kh + (size_t)(nn * NH + hh) * T * D;
    const float* Vh = g_Vh + (size_t)(nn * NH + hh) * T * D;

    __shared__ __align__(16) float Qtd[32][136];  /* [d][2q] duplicated pairs */
    __shared__ __align__(16) float Kt[32][68];    /* [d][k] */
    __shared__ __align__(16) float Vs[64][36];    /* [k][d] natural */
    __shared__ __align__(16) float Ps[64][68];    /* [q][k] */
    __shared__ float m_s[64], l_s[64], fs_s[64];

    int tid = threadIdx.x;
    int qg = tid >> 4, kg = tid & 15;     /* phase 1: 4q x 4k */
    int qp = tid >> 3, dp = tid & 7;      /* phase 2: 2q x 4d */

    /* Q fill: duplicated (q,q) pairs so phase-1 FFMA2 needs no packs */
    #pragma unroll
    for (int it = 0; it < 8; ++it) {
        int e = tid + it * 256;
        int r = e >> 5, c = e & 31;
        float v = Qh[(q0 + r) * D + c];
        *(float2*)&Qtd[c][2 * r] = make_float2(v, v);
    }
    if (tid < 64) { m_s[tid] = -1e30f; l_s[tid] = 0.0f; fs_s[tid] = 0.0f; }
    u64 O2[2][2] = {};                    /* [q-row][d-pair] */

    for (int kt = 0; kt < T / 64; ++kt) {
        int k0 = kt * 64;
        __syncthreads();
        #pragma unroll
        for (int it = 0; it < 8; ++it) {
            int e = tid + it * 256;
            int r = e >> 5, c = e & 31;
            Kt[c][r] = Kh[(k0 + r) * D + c];   /* transposed */
            Vs[r][c] = Vh[(k0 + r) * D + c];   /* natural    */
        }
        __syncthreads();

        /* ---- Phase 1: S = Q K^T via packed FFMA2 ---- */
        u64 acc2[4][2] = {};
        #pragma unroll
        for (int dd = 0; dd < 32; ++dd) {
            ulonglong2 qa = *(const ulonglong2*)&Qtd[dd][8 * qg];
            ulonglong2 qb = *(const ulonglong2*)&Qtd[dd][8 * qg + 4];
            ulonglong2 kk = *(const ulonglong2*)&Kt[dd][4 * kg];
            fma2(acc2[0][0], qa.x, kk.x); fma2(acc2[0][1], qa.x, kk.y);
            fma2(acc2[1][0], qa.y, kk.x); fma2(acc2[1][1], qa.y, kk.y);
            fma2(acc2[2][0], qb.x, kk.x); fma2(acc2[2][1], qb.x, kk.y);
            fma2(acc2[3][0], qb.y, kk.x); fma2(acc2[3][1], qb.y, kk.y);
        }
        float msk[4];
        #pragma unroll
        for (int j = 0; j < 4; ++j)
            msk[j] = g_kmask[nn * T + k0 + 4 * kg + j];

        #pragma unroll
        for (int i = 0; i < 4; ++i) {
            int q = 4 * qg + i;
            float2 lo = unpack2(acc2[i][0]), hi = unpack2(acc2[i][1]);
            float s0 = (msk[0] != 0.0f) ? lo.x * SCALE : NEGBIG;
            float s1 = (msk[1] != 0.0f) ? lo.y * SCALE : NEGBIG;
            float s2 = (msk[2] != 0.0f) ? hi.x * SCALE : NEGBIG;
            float s3 = (msk[3] != 0.0f) ? hi.y * SCALE : NEGBIG;
            float mx = fmaxf(fmaxf(s0, s1), fmaxf(s2, s3));
            #pragma unroll
            for (int o = 8; o; o >>= 1)
                mx = fmaxf(mx, __shfl_xor_sync(0xffffffffu, mx, o));
            float mo = m_s[q];
            float nm = fmaxf(mo, mx);
            float p0 = __expf(s0 - nm), p1 = __expf(s1 - nm);
            float p2 = __expf(s2 - nm), p3 = __expf(s3 - nm);
            float sum = (p0 + p1) + (p2 + p3);
            #pragma unroll
            for (int o = 8; o; o >>= 1)
                sum += __shfl_xor_sync(0xffffffffu, sum, o);
            /* key Tk-1 participates in softmax denom but not in ctx */
            float4 pw;
            pw.x = (k0 + 4*kg + 0 == T - 1) ? 0.0f : p0;
            pw.y = (k0 + 4*kg + 1 == T - 1) ? 0.0f : p1;
            pw.z = (k0 + 4*kg + 2 == T - 1) ? 0.0f : p2;
            pw.w = (k0 + 4*kg + 3 == T - 1) ? 0.0f : p3;
            *(float4*)&Ps[q][4 * kg] = pw;
            if (kg == 0) {
                float f = __expf(mo - nm);
                l_s[q]  = l_s[q] * f + sum;
                m_s[q]  = nm;
                fs_s[q] = f;
            }
        }
        __syncthreads();

        /* ---- Phase 2: O += P V, packed over d ---- */
        {
            float fA = fs_s[2 * qp],  fB = fs_s[2 * qp + 1];
            u64 fA2 = pack2(fA, fA),  fB2 = pack2(fB, fB);
            O2[0][0] = mul2(O2[0][0], fA2); O2[0][1] = mul2(O2[0][1], fA2);
            O2[1][0] = mul2(O2[1][0], fB2); O2[1][1] = mul2(O2[1][1], fB2);
        }
        #pragma unroll
        for (int kc = 0; kc < 64; kc += 4) {
            ulonglong2 v0 = *(const ulonglong2*)&Vs[kc + 0][4 * dp];
            ulonglong2 v1 = *(const ulonglong2*)&Vs[kc + 1][4 * dp];
            ulonglong2 v2 = *(const ulonglong2*)&Vs[kc + 2][4 * dp];
            ulonglong2 v3 = *(const ulonglong2*)&Vs[kc + 3][4 * dp];
            float4 pa = *(const float4*)&Ps[2 * qp][kc];
            float4 pb = *(const float4*)&Ps[2 * qp + 1][kc];
            u64 t;
            t = pack2(pa.x, pa.x); fma2(O2[0][0], t, v0.x); fma2(O2[0][1], t, v0.y);
            t = pack2(pa.y, pa.y); fma2(O2[0][0], t, v1.x); fma2(O2[0][1], t, v1.y);
            t = pack2(pa.z, pa.z); fma2(O2[0][0], t, v2.x); fma2(O2[0][1], t, v2.y);
            t = pack2(pa.w, pa.w); fma2(O2[0][0], t, v3.x); fma2(O2[0][1], t, v3.y);
            t = pack2(pb.x, pb.x); fma2(O2[1][0], t, v0.x); fma2(O2[1][1], t, v0.y);
            t = pack2(pb.y, pb.y); fma2(O2[1][0], t, v1.x); fma2(O2[1][1], t, v1.y);
            t = pack2(pb.z, pb.z); fma2(O2[1][0], t, v2.x); fma2(O2[1][1], t, v2.y);
            t = pack2(pb.w, pb.w); fma2(O2[1][0], t, v3.x); fma2(O2[1][1], t, v3.y);
        }
    }

    #pragma unroll
    for (int r = 0; r < 2; ++r) {
        int q = 2 * qp + r;
        float inv = g_qmask[nn * T + q0 + q] / l_s[q];
        float2 a = unpack2(O2[r][0]), b = unpack2(O2[r][1]);
        float4 o = make_float4(a.x * inv, a.y * inv, b.x * inv, b.y * inv);
        *(float4*)&g_ctx[(size_t)(nn * T + q0 + q) * H + hh * D + 4 * dp] = o;
    }
}

/* ------------------------------------------------------------------ */
__global__ void __launch_bounds__(256) ln_kernel(
        const float* __restrict__ gamma, const float* __restrict__ beta,
        float* __restrict__ out, float* __restrict__ wout) {
    int row = blockIdx.x;
    int t = threadIdx.x;
    float x = g_ctx[(size_t)row * H + t];
    __shared__ float rs[8], rq[8];
    float s = x, q = x * x;
    #pragma unroll
    for (int o = 16; o; o >>= 1) {
        s += __shfl_xor_sync(0xffffffffu, s, o);
        q += __shfl_xor_sync(0xffffffffu, q, o);
    }
    if ((t & 31) == 0) { rs[t >> 5] = s; rq[t >> 5] = q; }
    __syncthreads();
    float ts = 0.0f, tq = 0.0f;
    #pragma unroll
    for (int i = 0; i < 8; ++i) { ts += rs[i]; tq += rq[i]; }
    float mu  = ts * (1.0f / H);
    float var = tq * (1.0f / H) - mu * mu;
    float inv = rsqrtf(var + 1e-5f);
    out[(size_t)row * H + t] = (x - mu) * inv * gamma[t] + beta[t];
    if (t == 0)
        wout[row] = g_qmask[row] * (1.0f / (float)T);
}

/* ------------------------------------------------------------------ */
extern "C" void kernel_launch(void* const* d_in, const int* in_sizes, int n_in,
                              void* d_out, int out_size) {
    const float* Q  = (const float*)d_in[0];
    const float* K  = (const float*)d_in[1];
    const float* V  = (const float*)d_in[2];
    const float* Wq = (const float*)d_in[3];
    const float* bq = (const float*)d_in[4];
    const float* Wk = (const float*)d_in[5];
    const float* bk = (const float*)d_in[6];
    const float* Wv = (const float*)d_in[7];
    const float* bv = (const float*)d_in[8];
    const float* gamma = (const float*)d_in[9];
    const float* beta  = (const float*)d_in[10];

    float* out  = (float*)d_out;
    float* wout = out + (out_size - Nb * T);

    mask_kernel<<<dim3(Nb * T, 2), 128>>>(Q, K);
    proj_kernel<<<dim3(H / 64, (Nb * T) / 64, 3), 256>>>(Q, K, V,
                                                         Wq, Wk, Wv,
                                                         bq, bk, bv);
    attn_kernel<<<dim3(T / 64, NH, Nb), 256>>>();
    ln_kernel<<<Nb * T, 256>>>(gamma, beta, out, wout);
}